// round 1
// baseline (speedup 1.0000x reference)
#include <cuda_runtime.h>

#define GN 262144   // 64*64*64 spatial
#define CC 256      // Cin = Cout = R

// Scratch buffers (allocation-free rule: __device__ globals)
__device__ float g_y [(size_t)CC * GN];
__device__ float g_y2[(size_t)CC * GN];

// ---------------------------------------------------------------------------
// GEMM: Y[m, n] = sum_k A[k*256 + m] * X[k*GN + n]  (+ bias[m] if BIAS)
// A is k-major [256, 256]; X is [256, GN]; Y is [256, GN].
// Tile: BM=128, BN=64, BK=16. 256 threads, each computes 8x4 outputs.
// ---------------------------------------------------------------------------
template<bool BIAS>
__global__ __launch_bounds__(256) void gemm_kernel(
    const float* __restrict__ A,
    const float* __restrict__ X,
    float* __restrict__ Y,
    const float* __restrict__ bias)
{
    __shared__ float As[16][128];
    __shared__ float Xs[16][68];   // pitch 68 keeps float4 alignment, pads banks

    const int tid = threadIdx.x;
    const int n0 = blockIdx.x * 64;
    const int m0 = blockIdx.y * 128;
    const int ty = tid >> 4;   // 0..15 -> 8 m-rows each
    const int tx = tid & 15;   // 0..15 -> 4 n-cols each

    float acc[8][4];
#pragma unroll
    for (int i = 0; i < 8; i++)
#pragma unroll
        for (int j = 0; j < 4; j++) acc[i][j] = 0.f;

    for (int kk = 0; kk < 256; kk += 16) {
        // Load A tile: 16x128 floats = 512 float4, 2 per thread
#pragma unroll
        for (int i = 0; i < 2; i++) {
            int v  = tid + i * 256;
            int k  = v >> 5;          // 32 float4 per row
            int m4 = (v & 31) << 2;
            *(float4*)&As[k][m4] =
                *(const float4*)&A[(kk + k) * 256 + m0 + m4];
        }
        // Load X tile: 16x64 floats = 256 float4, 1 per thread
        {
            int k  = tid >> 4;
            int n4 = (tid & 15) << 2;
            *(float4*)&Xs[k][n4] =
                *(const float4*)&X[(size_t)(kk + k) * GN + n0 + n4];
        }
        __syncthreads();

#pragma unroll
        for (int k = 0; k < 16; k++) {
            float4 b  = *(float4*)&Xs[k][tx << 2];
            float4 a0 = *(float4*)&As[k][ty << 3];
            float4 a1 = *(float4*)&As[k][(ty << 3) + 4];
            float av[8] = {a0.x, a0.y, a0.z, a0.w, a1.x, a1.y, a1.z, a1.w};
            float bv[4] = {b.x, b.y, b.z, b.w};
#pragma unroll
            for (int i = 0; i < 8; i++)
#pragma unroll
                for (int j = 0; j < 4; j++) acc[i][j] += av[i] * bv[j];
        }
        __syncthreads();
    }

#pragma unroll
    for (int i = 0; i < 8; i++) {
        int m = m0 + (ty << 3) + i;
        float bv = BIAS ? bias[m] : 0.f;
        float4 o;
        o.x = acc[i][0] + bv;
        o.y = acc[i][1] + bv;
        o.z = acc[i][2] + bv;
        o.w = acc[i][3] + bv;
        *(float4*)&Y[(size_t)m * GN + n0 + (tx << 2)] = o;
    }
}

// ---------------------------------------------------------------------------
// Fused separable 3D conv (3 taps per axis, zero pad 1, stride 1), per rank r:
//   z[h,w,d] = sum_{a,b,c} Ukh[a][r]*Ukw[b][r]*Ukd[c][r] * y[h+a-1, w+b-1, d+c-1]
// Block: one r, one 8x8 (h,w) tile, full d=64 line.
// Shared halo tile 10x10x64 (pitch 65); separable contraction h,w in registers
// over an 18-wide d window, then d-contraction; results staged through padded
// shared memory for fully coalesced global stores.
// ---------------------------------------------------------------------------
__global__ __launch_bounds__(256) void conv3_kernel(
    const float* __restrict__ Yin,
    float* __restrict__ Z,
    const float* __restrict__ Ukh,
    const float* __restrict__ Ukw,
    const float* __restrict__ Ukd)
{
    __shared__ float s[6500];    // [hh 0..9][ww 0..9][d 0..63], pitch 65
    __shared__ float s2[4160];   // [hw 0..63][d 0..63], pitch 65

    const int r  = blockIdx.y;
    const int h0 = (blockIdx.x >> 3) * 8 - 1;   // halo origin in h
    const int w0 = (blockIdx.x & 7) * 8 - 1;    // halo origin in w

    const float* src = Yin + (size_t)r * GN;

    // Load 10x10x64 halo tile (zero-fill out-of-range h/w)
    for (int i = threadIdx.x; i < 6400; i += 256) {
        int d  = i & 63;
        int hw = i >> 6;           // 0..99
        int hh = hw / 10;
        int ww = hw - hh * 10;
        int h = h0 + hh, w = w0 + ww;
        float v = 0.f;
        if ((unsigned)h < 64u && (unsigned)w < 64u)
            v = src[(h << 12) + (w << 6) + d];
        s[hw * 65 + d] = v;
    }

    const float ch0 = Ukh[r],       ch1 = Ukh[256 + r], ch2 = Ukh[512 + r];
    const float cw0 = Ukw[r],       cw1 = Ukw[256 + r], cw2 = Ukw[512 + r];
    const float cd0 = Ukd[r],       cd1 = Ukd[256 + r], cd2 = Ukd[512 + r];

    __syncthreads();

    const int q  = threadIdx.x >> 6;   // d-chunk 0..3 (16 d each)
    const int rc = threadIdx.x & 63;
    const int oh = rc >> 3;            // 0..7
    const int ow = rc & 7;             // 0..7

    const float* p0 = &s[(oh * 10 + ow) * 65];

    // h,w contraction over an 18-wide d window (halo 1 each side)
    float tmp[18];
    const int dbase = q * 16 - 1;
#pragma unroll
    for (int j = 0; j < 18; j++) {
        int d = dbase + j;
        float v = 0.f;
        if ((unsigned)d < 64u) {
            const float* p = p0 + d;
            v = ch0 * (cw0 * p[0]    + cw1 * p[65]   + cw2 * p[130])
              + ch1 * (cw0 * p[650]  + cw1 * p[715]  + cw2 * p[780])
              + ch2 * (cw0 * p[1300] + cw1 * p[1365] + cw2 * p[1430]);
        }
        tmp[j] = v;
    }

    // d contraction -> staged shared (pitch 65 avoids bank conflicts)
    float* st = &s2[rc * 65 + q * 16];
#pragma unroll
    for (int j = 0; j < 16; j++)
        st[j] = cd0 * tmp[j] + cd1 * tmp[j + 1] + cd2 * tmp[j + 2];

    __syncthreads();

    // Coalesced copy-out
    float* dst = Z + (size_t)r * GN;
    const int hb = h0 + 1, wb = w0 + 1;
    for (int i = threadIdx.x; i < 4096; i += 256) {
        int d  = i & 63;
        int hw = i >> 6;           // 0..63
        int ohh = hw >> 3;
        int oww = hw & 7;
        dst[((hb + ohh) << 12) + ((wb + oww) << 6) + d] = s2[hw * 65 + d];
    }
}

// ---------------------------------------------------------------------------
extern "C" void kernel_launch(void* const* d_in, const int* in_sizes, int n_in,
                              void* d_out, int out_size)
{
    const float* x      = (const float*)d_in[0];
    const float* U_kh   = (const float*)d_in[1];
    const float* U_kw   = (const float*)d_in[2];
    const float* U_kd   = (const float*)d_in[3];
    const float* U_cin  = (const float*)d_in[4];
    const float* U_cout = (const float*)d_in[5];
    const float* bias   = (const float*)d_in[6];
    float* out = (float*)d_out;

    float *y, *y2;
    cudaGetSymbolAddress((void**)&y,  g_y);
    cudaGetSymbolAddress((void**)&y2, g_y2);

    dim3 ggrid(GN / 64, 2);   // 4096 x 2 blocks

    // Stage 1: y[r, s] = sum_c U_cin[c, r] * x[c, s]
    gemm_kernel<false><<<ggrid, 256>>>(U_cin, x, y, nullptr);

    // Stage 2: fused separable 3x3x3 conv per rank
    conv3_kernel<<<dim3(64, 256), 256>>>(y, y2, U_kh, U_kw, U_kd);

    // Stage 3: out[co, s] = sum_r U_cout[r, co] * y2[r, s] + bias[co]
    gemm_kernel<true><<<ggrid, 256>>>(U_cout, y2, out, bias);
}

// round 3
// speedup vs baseline: 1.2267x; 1.2267x over previous
#include <cuda_runtime.h>
#include <cstdint>

#define GN 262144   // 64*64*64 spatial
#define CC 256      // Cin = Cout = R

// Scratch buffers (allocation-free rule: __device__ globals)
__device__ float g_y [(size_t)CC * GN];
__device__ float g_y2[(size_t)CC * GN];

#define AP 136   // As pitch (8-mod-32 banks -> conflict-free frag loads)
#define BP 72    // Bs pitch (same property)

// ---------------------------------------------------------------------------
// TF32 tensor-core GEMM with 3xTF32 precision recovery.
// Y[m, n] = sum_k A[k*256 + m] * X[k*GN + n]  (+ bias[m] if BIAS)
// Tiles: BM=128, BN=64, BK=32. 256 threads = 8 warps (2m x 4n), warp = 64x16.
// ---------------------------------------------------------------------------
template<bool BIAS>
__global__ __launch_bounds__(256) void gemm_tf32_kernel(
    const float* __restrict__ A,
    const float* __restrict__ X,
    float* __restrict__ Y,
    const float* __restrict__ bias)
{
    __shared__ float As[32 * AP];
    __shared__ float Bs[32 * BP];

    const int tid  = threadIdx.x;
    const int lane = tid & 31;
    const int warp = tid >> 5;
    const int n0 = blockIdx.x * 64;
    const int m0 = blockIdx.y * 128;
    const int wm = (warp & 1) * 64;      // warp m-offset
    const int wn = (warp >> 1) * 16;     // warp n-offset
    const int g  = lane >> 2;            // octet group 0..7
    const int tg = lane & 3;             // 0..3

    float c[4][2][4];
#pragma unroll
    for (int mt = 0; mt < 4; mt++)
#pragma unroll
        for (int nt = 0; nt < 2; nt++)
#pragma unroll
            for (int i = 0; i < 4; i++) c[mt][nt][i] = 0.f;

    for (int kt = 0; kt < 256; kt += 32) {
        // A tile 32x128 -> As[k][m] : 1024 float4, 4 per thread
#pragma unroll
        for (int i = 0; i < 4; i++) {
            int v  = tid + i * 256;
            int k  = v >> 5;
            int m4 = (v & 31) << 2;
            *(float4*)&As[k * AP + m4] =
                *(const float4*)&A[(kt + k) * 256 + m0 + m4];
        }
        // B tile 32x64 -> Bs[k][n] : 512 float4, 2 per thread
#pragma unroll
        for (int i = 0; i < 2; i++) {
            int v  = tid + i * 256;
            int k  = v >> 4;
            int n4 = (v & 15) << 2;
            *(float4*)&Bs[k * BP + n4] =
                *(const float4*)&X[(size_t)(kt + k) * GN + n0 + n4];
        }
        __syncthreads();

#pragma unroll
        for (int k8 = 0; k8 < 32; k8 += 8) {
            // A fragments, split into tf32 hi/lo
            uint32_t ahi[4][4], alo[4][4];
#pragma unroll
            for (int mt = 0; mt < 4; mt++) {
#pragma unroll
                for (int j = 0; j < 4; j++) {
                    int m = wm + mt * 16 + g + ((j & 1) << 3);
                    int k = k8 + tg + ((j >> 1) << 2);
                    float a = As[k * AP + m];
                    uint32_t h = __float_as_uint(a) & 0xFFFFE000u;
                    ahi[mt][j] = h;
                    alo[mt][j] = __float_as_uint(a - __uint_as_float(h));
                }
            }
            // B fragments, hi/lo
            uint32_t bhi[2][2], blo[2][2];
#pragma unroll
            for (int nt = 0; nt < 2; nt++) {
#pragma unroll
                for (int j = 0; j < 2; j++) {
                    int n = wn + nt * 8 + g;
                    int k = k8 + tg + (j << 2);
                    float b = Bs[k * BP + n];
                    uint32_t h = __float_as_uint(b) & 0xFFFFE000u;
                    bhi[nt][j] = h;
                    blo[nt][j] = __float_as_uint(b - __uint_as_float(h));
                }
            }
#pragma unroll
            for (int mt = 0; mt < 4; mt++) {
#pragma unroll
                for (int nt = 0; nt < 2; nt++) {
#define MMA_TF32(CF, AF, BF)                                                   \
    asm volatile(                                                              \
        "mma.sync.aligned.m16n8k8.row.col.f32.tf32.tf32.f32 "                  \
        "{%0,%1,%2,%3}, {%4,%5,%6,%7}, {%8,%9}, {%0,%1,%2,%3};\n"              \
        : "+f"(CF[0]), "+f"(CF[1]), "+f"(CF[2]), "+f"(CF[3])                   \
        : "r"(AF[0]), "r"(AF[1]), "r"(AF[2]), "r"(AF[3]),                      \
          "r"(BF[0]), "r"(BF[1]))
                    MMA_TF32(c[mt][nt], ahi[mt], bhi[nt]);
                    MMA_TF32(c[mt][nt], ahi[mt], blo[nt]);
                    MMA_TF32(c[mt][nt], alo[mt], bhi[nt]);
                }
            }
        }
        __syncthreads();
    }

    // Epilogue: c0/c1 -> row g, c2/c3 -> row g+8; cols tg*2, tg*2+1
#pragma unroll
    for (int mt = 0; mt < 4; mt++) {
#pragma unroll
        for (int half = 0; half < 2; half++) {
            int m = m0 + wm + mt * 16 + g + half * 8;
            float bv = BIAS ? bias[m] : 0.f;
#pragma unroll
            for (int nt = 0; nt < 2; nt++) {
                float2 o;
                o.x = c[mt][nt][half * 2 + 0] + bv;
                o.y = c[mt][nt][half * 2 + 1] + bv;
                *(float2*)&Y[(size_t)m * GN + n0 + wn + nt * 8 + tg * 2] = o;
            }
        }
    }
}

// ---------------------------------------------------------------------------
// Fused separable 3D conv (3 taps per axis, zero pad 1, stride 1), per rank r.
// Block: one r, one 8x8 (h,w) tile, full d=64 line. Unchanged from R1.
// ---------------------------------------------------------------------------
__global__ __launch_bounds__(256) void conv3_kernel(
    const float* __restrict__ Yin,
    float* __restrict__ Z,
    const float* __restrict__ Ukh,
    const float* __restrict__ Ukw,
    const float* __restrict__ Ukd)
{
    __shared__ float s[6500];    // [hh 0..9][ww 0..9][d 0..63], pitch 65
    __shared__ float s2[4160];   // [hw 0..63][d 0..63], pitch 65

    const int r  = blockIdx.y;
    const int h0 = (blockIdx.x >> 3) * 8 - 1;
    const int w0 = (blockIdx.x & 7) * 8 - 1;

    const float* src = Yin + (size_t)r * GN;

    for (int i = threadIdx.x; i < 6400; i += 256) {
        int d  = i & 63;
        int hw = i >> 6;
        int hh = hw / 10;
        int ww = hw - hh * 10;
        int h = h0 + hh, w = w0 + ww;
        float v = 0.f;
        if ((unsigned)h < 64u && (unsigned)w < 64u)
            v = src[(h << 12) + (w << 6) + d];
        s[hw * 65 + d] = v;
    }

    const float ch0 = Ukh[r], ch1 = Ukh[256 + r], ch2 = Ukh[512 + r];
    const float cw0 = Ukw[r], cw1 = Ukw[256 + r], cw2 = Ukw[512 + r];
    const float cd0 = Ukd[r], cd1 = Ukd[256 + r], cd2 = Ukd[512 + r];

    __syncthreads();

    const int q  = threadIdx.x >> 6;
    const int rc = threadIdx.x & 63;
    const int oh = rc >> 3;
    const int ow = rc & 7;

    const float* p0 = &s[(oh * 10 + ow) * 65];

    float tmp[18];
    const int dbase = q * 16 - 1;
#pragma unroll
    for (int j = 0; j < 18; j++) {
        int d = dbase + j;
        float v = 0.f;
        if ((unsigned)d < 64u) {
            const float* p = p0 + d;
            v = ch0 * (cw0 * p[0]    + cw1 * p[65]   + cw2 * p[130])
              + ch1 * (cw0 * p[650]  + cw1 * p[715]  + cw2 * p[780])
              + ch2 * (cw0 * p[1300] + cw1 * p[1365] + cw2 * p[1430]);
        }
        tmp[j] = v;
    }

    float* st = &s2[rc * 65 + q * 16];
#pragma unroll
    for (int j = 0; j < 16; j++)
        st[j] = cd0 * tmp[j] + cd1 * tmp[j + 1] + cd2 * tmp[j + 2];

    __syncthreads();

    float* dst = Z + (size_t)r * GN;
    const int hb = h0 + 1, wb = w0 + 1;
    for (int i = threadIdx.x; i < 4096; i += 256) {
        int d  = i & 63;
        int hw = i >> 6;
        int ohh = hw >> 3;
        int oww = hw & 7;
        dst[((hb + ohh) << 12) + ((wb + oww) << 6) + d] = s2[hw * 65 + d];
    }
}

// ---------------------------------------------------------------------------
extern "C" void kernel_launch(void* const* d_in, const int* in_sizes, int n_in,
                              void* d_out, int out_size)
{
    const float* x      = (const float*)d_in[0];
    const float* U_kh   = (const float*)d_in[1];
    const float* U_kw   = (const float*)d_in[2];
    const float* U_kd   = (const float*)d_in[3];
    const float* U_cin  = (const float*)d_in[4];
    const float* U_cout = (const float*)d_in[5];
    const float* bias   = (const float*)d_in[6];
    float* out = (float*)d_out;

    float *y, *y2;
    cudaGetSymbolAddress((void**)&y,  g_y);
    cudaGetSymbolAddress((void**)&y2, g_y2);

    dim3 ggrid(GN / 64, 2);   // 4096 x 2 blocks

    // Stage 1: y[r, s] = sum_c U_cin[c, r] * x[c, s]
    gemm_tf32_kernel<false><<<ggrid, 256>>>(U_cin, x, y, nullptr);

    // Stage 2: fused separable 3x3x3 conv per rank
    conv3_kernel<<<dim3(64, 256), 256>>>(y, y2, U_kh, U_kw, U_kd);

    // Stage 3: out[co, s] = sum_r U_cout[r, co] * y2[r, s] + bias[co]
    gemm_tf32_kernel<true><<<ggrid, 256>>>(U_cout, y2, out, bias);
}